// round 2
// baseline (speedup 1.0000x reference)
#include <cuda_runtime.h>
#include <cuda_bf16.h>
#include <cstdint>

// Problem constants
#define BATCH 2
#define SLEN 2048
#define DMODEL 1024
#define HEADS 16
#define HD 64
#define QT 128   // query tile (rows per attention block)
#define KT 64    // key tile

// Scratch: device globals (no allocations allowed in kernel_launch)
__device__ float g_qkv[BATCH * SLEN * 3 * DMODEL];   // [B,S,3D]  ~48 MB
__device__ float g_att[BATCH * SLEN * DMODEL];       // [B,S,D]   ~16 MB

// ---------------------------------------------------------------------------
// Classic 128x128x8 SGEMM, 8x8 microtile, 256 threads.
// C[M,N] = A[M,K] @ B[K,N], all row-major, M%128==0, N%128==0, K%8==0.
// ---------------------------------------------------------------------------
__global__ __launch_bounds__(256) void sgemm128(
    const float* __restrict__ A, const float* __restrict__ B,
    float* __restrict__ C, int M, int N, int K)
{
    __shared__ float As[8][128];   // transposed A tile
    __shared__ float Bs[8][128];

    const int tid = threadIdx.x;
    const int tx = tid % 16;       // column group
    const int ty = tid / 16;       // row group
    const int brow = blockIdx.y * 128;
    const int bcol = blockIdx.x * 128;

    float acc[8][8];
    #pragma unroll
    for (int i = 0; i < 8; i++)
        #pragma unroll
        for (int j = 0; j < 8; j++) acc[i][j] = 0.f;

    const int arow = tid / 2;      // 0..127  (A tile row)
    const int ac4  = tid % 2;      // 0..1    (which float4 of the 8-wide k slab)
    const int brl  = tid / 32;     // 0..7    (B tile row = k)
    const int bc4  = tid % 32;     // 0..31   (float4 within 128-wide row)

    const float4* A4 = reinterpret_cast<const float4*>(A);
    const float4* B4 = reinterpret_cast<const float4*>(B);

    for (int k0 = 0; k0 < K; k0 += 8) {
        // Load A 128x8 (transposed into As), coalesced float4
        float4 a = A4[((size_t)(brow + arow) * K + k0) / 4 + ac4];
        As[ac4 * 4 + 0][arow] = a.x;
        As[ac4 * 4 + 1][arow] = a.y;
        As[ac4 * 4 + 2][arow] = a.z;
        As[ac4 * 4 + 3][arow] = a.w;
        // Load B 8x128, coalesced float4
        float4 bv = B4[((size_t)(k0 + brl) * N + bcol) / 4 + bc4];
        reinterpret_cast<float4*>(&Bs[brl][0])[bc4] = bv;
        __syncthreads();

        #pragma unroll
        for (int k = 0; k < 8; k++) {
            float ar[8], br[8];
            #pragma unroll
            for (int i = 0; i < 8; i++) ar[i] = As[k][ty * 8 + i];
            #pragma unroll
            for (int j = 0; j < 8; j++) br[j] = Bs[k][tx * 8 + j];
            #pragma unroll
            for (int i = 0; i < 8; i++)
                #pragma unroll
                for (int j = 0; j < 8; j++)
                    acc[i][j] += ar[i] * br[j];
        }
        __syncthreads();
    }

    #pragma unroll
    for (int i = 0; i < 8; i++) {
        float* cr = C + (size_t)(brow + ty * 8 + i) * N + bcol + tx * 8;
        float4 c0 = make_float4(acc[i][0], acc[i][1], acc[i][2], acc[i][3]);
        float4 c1 = make_float4(acc[i][4], acc[i][5], acc[i][6], acc[i][7]);
        reinterpret_cast<float4*>(cr)[0] = c0;
        reinterpret_cast<float4*>(cr)[1] = c1;
    }
}

// ---------------------------------------------------------------------------
// Causal flash attention, fp32.
// qkv layout: [B, S, 3*DMODEL]; q cols [0,D), k cols [D,2D), v cols [2D,3D).
// Head h occupies columns h*HD within its segment.
// Grid: (S/QT, HEADS, BATCH). Block: 128 threads, 1 query row per thread.
// Output: att[B, S, DMODEL] with head h at cols h*HD.
// Static smem = 32 KB (sK + sV) -> fits the 48 KB static cap, 2 blocks/SM.
// ---------------------------------------------------------------------------
__global__ __launch_bounds__(128) void flash_kernel(
    const float* __restrict__ qkv, float* __restrict__ out)
{
    __shared__ float sK[KT * HD];   // 16 KB
    __shared__ float sV[KT * HD];   // 16 KB

    const int t  = threadIdx.x;          // 0..127
    const int q0 = blockIdx.x * QT;
    const int h  = blockIdx.y;
    const int b  = blockIdx.z;

    const float* base = qkv + (size_t)b * SLEN * 3 * DMODEL + h * HD;
    const int qi = q0 + t;

    // Load this thread's query row directly from gmem (16 contiguous float4).
    float q[HD];
    {
        const float4* q4 = reinterpret_cast<const float4*>(base + (size_t)qi * 3 * DMODEL);
        #pragma unroll
        for (int d4 = 0; d4 < HD / 4; d4++) {
            float4 v = q4[d4];
            q[4 * d4 + 0] = v.x;
            q[4 * d4 + 1] = v.y;
            q[4 * d4 + 2] = v.z;
            q[4 * d4 + 3] = v.w;
        }
    }

    float m = -INFINITY, l = 0.f;
    float acc[HD];
    #pragma unroll
    for (int d = 0; d < HD; d++) acc[d] = 0.f;

    const float scale = 0.125f;  // 1/sqrt(64)

    for (int k0 = 0; k0 < q0 + QT; k0 += KT) {
        __syncthreads();
        // Stage K and V tiles (coalesced)
        const float* kb = base + (size_t)k0 * 3 * DMODEL + DMODEL;
        const float* vb = kb + DMODEL;
        for (int i = t; i < KT * (HD / 4); i += 128) {
            int r = i / (HD / 4), c = i % (HD / 4);
            reinterpret_cast<float4*>(sK)[i] =
                reinterpret_cast<const float4*>(kb + (size_t)r * 3 * DMODEL)[c];
            reinterpret_cast<float4*>(sV)[i] =
                reinterpret_cast<const float4*>(vb + (size_t)r * 3 * DMODEL)[c];
        }
        __syncthreads();

        // Process keys in chunks of 16 (online softmax)
        for (int j0 = 0; j0 < KT; j0 += 16) {
            if (k0 + j0 > qi) break;   // fully masked chunk for this query
            float sv[16];
            float mc = -INFINITY;
            #pragma unroll
            for (int jj = 0; jj < 16; jj++) {
                const int j = j0 + jj;
                const float4* K4 = reinterpret_cast<const float4*>(sK + j * HD);
                float s0 = 0.f, s1 = 0.f, s2 = 0.f, s3 = 0.f;
                #pragma unroll
                for (int d4 = 0; d4 < HD / 4; d4++) {
                    float4 kk = K4[d4];   // warp-uniform address -> smem broadcast
                    s0 += q[4 * d4 + 0] * kk.x;
                    s1 += q[4 * d4 + 1] * kk.y;
                    s2 += q[4 * d4 + 2] * kk.z;
                    s3 += q[4 * d4 + 3] * kk.w;
                }
                float s = ((s0 + s1) + (s2 + s3)) * scale;
                if (k0 + j > qi) s = -INFINITY;
                sv[jj] = s;
                mc = fmaxf(mc, s);
            }
            const float mnew = fmaxf(m, mc);
            const float corr = __expf(m - mnew);   // m=-inf -> 0 on first chunk
            l *= corr;
            #pragma unroll
            for (int d = 0; d < HD; d++) acc[d] *= corr;
            #pragma unroll
            for (int jj = 0; jj < 16; jj++) {
                const int j = j0 + jj;
                const float p = (k0 + j <= qi) ? __expf(sv[jj] - mnew) : 0.f;
                l += p;
                const float4* V4 = reinterpret_cast<const float4*>(sV + j * HD);
                #pragma unroll
                for (int d4 = 0; d4 < HD / 4; d4++) {
                    float4 vv = V4[d4];
                    acc[4 * d4 + 0] += p * vv.x;
                    acc[4 * d4 + 1] += p * vv.y;
                    acc[4 * d4 + 2] += p * vv.z;
                    acc[4 * d4 + 3] += p * vv.w;
                }
            }
            m = mnew;
        }
    }

    const float inv = 1.f / l;
    float* ob = out + ((size_t)(b * SLEN + qi)) * DMODEL + h * HD;
    #pragma unroll
    for (int d4 = 0; d4 < HD / 4; d4++) {
        float4 o = make_float4(acc[4 * d4 + 0] * inv, acc[4 * d4 + 1] * inv,
                               acc[4 * d4 + 2] * inv, acc[4 * d4 + 3] * inv);
        reinterpret_cast<float4*>(ob)[d4] = o;
    }
}

// ---------------------------------------------------------------------------
// kernel_launch: qkv GEMM -> flash attention -> output GEMM
// Inputs: d_in[0]=x [B,S,D] f32, d_in[1]=w_qkv [D,3D] f32, d_in[2]=w_out [D,D] f32
// Output: [B,S,D] f32
// ---------------------------------------------------------------------------
extern "C" void kernel_launch(void* const* d_in, const int* in_sizes, int n_in,
                              void* d_out, int out_size)
{
    const float* x     = (const float*)d_in[0];
    const float* w_qkv = (const float*)d_in[1];
    const float* w_out = (const float*)d_in[2];
    float* out = (float*)d_out;

    float* qkv = nullptr;
    float* att = nullptr;
    cudaGetSymbolAddress((void**)&qkv, g_qkv);
    cudaGetSymbolAddress((void**)&att, g_att);

    const int M = BATCH * SLEN;   // 4096

    // 1) qkv = x @ w_qkv   [4096,1024]x[1024,3072]
    sgemm128<<<dim3((3 * DMODEL) / 128, M / 128), 256>>>(x, w_qkv, qkv, M, 3 * DMODEL, DMODEL);

    // 2) causal flash attention per (b,h, 128-query tile)
    flash_kernel<<<dim3(SLEN / QT, HEADS, BATCH), 128>>>(qkv, att);

    // 3) out = att @ w_out  [4096,1024]x[1024,1024]
    sgemm128<<<dim3(DMODEL / 128, M / 128), 256>>>(att, w_out, out, M, DMODEL, DMODEL);
}

// round 4
// speedup vs baseline: 1.4324x; 1.4324x over previous
#include <cuda_runtime.h>
#include <cuda_bf16.h>
#include <cstdint>

// Problem constants
#define BATCH 2
#define SLEN 2048
#define DMODEL 1024
#define HEADS 16
#define HD 64
#define QT 128
#define KT 64
#define MDIM (BATCH * SLEN)   // 4096

// ---------------------------------------------------------------------------
// Scratch (device globals; no allocations allowed)
// ---------------------------------------------------------------------------
__device__ float g_qkv[(size_t)MDIM * 3 * DMODEL];            // 48 MB
__device__ float g_att[(size_t)MDIM * DMODEL];                // 16 MB
__device__ __nv_bfloat16 g_xhi[(size_t)MDIM * DMODEL];
__device__ __nv_bfloat16 g_xlo[(size_t)MDIM * DMODEL];
__device__ __nv_bfloat16 g_w1hi[(size_t)3 * DMODEL * DMODEL]; // w_qkv^T [3D, D]
__device__ __nv_bfloat16 g_w1lo[(size_t)3 * DMODEL * DMODEL];
__device__ __nv_bfloat16 g_w2hi[(size_t)DMODEL * DMODEL];     // w_out^T [D, D]
__device__ __nv_bfloat16 g_w2lo[(size_t)DMODEL * DMODEL];
__device__ __nv_bfloat16 g_ahi[(size_t)MDIM * DMODEL];
__device__ __nv_bfloat16 g_alo[(size_t)MDIM * DMODEL];

// ---------------------------------------------------------------------------
// PTX helpers (sm_80+ instructions only — harness targets base sm_100)
// ---------------------------------------------------------------------------
__device__ __forceinline__ uint32_t smem_u32(const void* p) {
    uint32_t a;
    asm("{ .reg .u64 t; cvta.to.shared.u64 t, %1; cvt.u32.u64 %0, t; }" : "=r"(a) : "l"(p));
    return a;
}

__device__ __forceinline__ void cp16(uint32_t dst, const void* src) {
    asm volatile("cp.async.cg.shared.global [%0], [%1], 16;" :: "r"(dst), "l"(src) : "memory");
}
#define CP_COMMIT() asm volatile("cp.async.commit_group;" ::: "memory")
#define CP_WAIT(n)  asm volatile("cp.async.wait_group %0;" :: "n"(n) : "memory")

#define LDM4(r, addr) \
    asm volatile("ldmatrix.sync.aligned.m8n8.x4.shared.b16 {%0,%1,%2,%3}, [%4];" \
        : "=r"((r)[0]), "=r"((r)[1]), "=r"((r)[2]), "=r"((r)[3]) : "r"(addr))

#define MMA(d, a, b0, b1) \
    asm volatile("mma.sync.aligned.m16n8k16.row.col.f32.bf16.bf16.f32 " \
        "{%0,%1,%2,%3}, {%4,%5,%6,%7}, {%8,%9}, {%0,%1,%2,%3};" \
        : "+f"((d)[0]), "+f"((d)[1]), "+f"((d)[2]), "+f"((d)[3]) \
        : "r"((a)[0]), "r"((a)[1]), "r"((a)[2]), "r"((a)[3]), "r"(b0), "r"(b1))

// ---------------------------------------------------------------------------
// Split fp32 -> (hi, lo) bf16, elementwise (vectorized by 4)
// ---------------------------------------------------------------------------
__global__ __launch_bounds__(256) void split_fp32(
    const float* __restrict__ src, __nv_bfloat16* __restrict__ hi,
    __nv_bfloat16* __restrict__ lo, int n4)
{
    int i = blockIdx.x * blockDim.x + threadIdx.x;
    if (i >= n4) return;
    float4 v = reinterpret_cast<const float4*>(src)[i];
    float f[4] = {v.x, v.y, v.z, v.w};
    __nv_bfloat16 h[4], l[4];
    #pragma unroll
    for (int j = 0; j < 4; j++) {
        h[j] = __float2bfloat16(f[j]);
        l[j] = __float2bfloat16(f[j] - __bfloat162float(h[j]));
    }
    __nv_bfloat162 h01 = __halves2bfloat162(h[0], h[1]);
    __nv_bfloat162 h23 = __halves2bfloat162(h[2], h[3]);
    __nv_bfloat162 l01 = __halves2bfloat162(l[0], l[1]);
    __nv_bfloat162 l23 = __halves2bfloat162(l[2], l[3]);
    uint2 hp = make_uint2(*(uint32_t*)&h01, *(uint32_t*)&h23);
    uint2 lp = make_uint2(*(uint32_t*)&l01, *(uint32_t*)&l23);
    reinterpret_cast<uint2*>(hi)[i] = hp;
    reinterpret_cast<uint2*>(lo)[i] = lp;
}

// ---------------------------------------------------------------------------
// Split + transpose: src [R, C] fp32 -> hiT, loT [C, R] bf16
// ---------------------------------------------------------------------------
__global__ __launch_bounds__(256) void split_transpose(
    const float* __restrict__ src, __nv_bfloat16* __restrict__ hiT,
    __nv_bfloat16* __restrict__ loT, int R, int C)
{
    __shared__ float t[32][33];
    const int c0 = blockIdx.x * 32, r0 = blockIdx.y * 32;
    const int tx = threadIdx.x, ty = threadIdx.y;   // 32 x 8
    #pragma unroll
    for (int j = 0; j < 4; j++)
        t[ty + 8 * j][tx] = src[(size_t)(r0 + ty + 8 * j) * C + c0 + tx];
    __syncthreads();
    #pragma unroll
    for (int j = 0; j < 4; j++) {
        float v = t[tx][ty + 8 * j];
        __nv_bfloat16 h = __float2bfloat16(v);
        __nv_bfloat16 l = __float2bfloat16(v - __bfloat162float(h));
        size_t o = (size_t)(c0 + ty + 8 * j) * R + r0 + tx;
        hiT[o] = h;
        loT[o] = l;
    }
}

// ---------------------------------------------------------------------------
// Warp-MMA GEMM with fp32 emulation via 3-term bf16 split.
// C[M,N] = A[M,K] @ B[K,N], given Ahi/Alo [M,K] and BThi/BTlo [N,K] (bf16).
// CTA tile 128x128, 8 warps (64x32 each), K chunks of 64, cp.async x2 stages.
// SMEM rows padded to 144 B -> conflict-free ldmatrix.
// ---------------------------------------------------------------------------
#define MAT_BYTES 18432        // 128 rows * 144 B
#define STAGE_BYTES 73728      // 4 matrices
#define GSMEM_BYTES 147456     // 2 stages

__global__ __launch_bounds__(256, 1) void gemm_mma3(
    const __nv_bfloat16* __restrict__ Ahi, const __nv_bfloat16* __restrict__ Alo,
    const __nv_bfloat16* __restrict__ BThi, const __nv_bfloat16* __restrict__ BTlo,
    float* __restrict__ C, int M, int N, int K)
{
    extern __shared__ char smem[];
    const uint32_t sb = smem_u32(smem);
    const int tid = threadIdx.x;
    const int wid = tid >> 5, lane = tid & 31;
    const int m0 = blockIdx.y << 7, n0 = blockIdx.x << 7;
    const int wm = (wid >> 2) * 64;     // warp M offset (2 rows of warps)
    const int wn = (wid & 3) * 32;      // warp N offset (4 cols of warps)
    const int nc = K >> 6;

    const __nv_bfloat16* gsrc[4] = {
        Ahi + (size_t)m0 * K, Alo + (size_t)m0 * K,
        BThi + (size_t)n0 * K, BTlo + (size_t)n0 * K };

    float acc[4][4][4];
    #pragma unroll
    for (int a = 0; a < 4; a++)
        #pragma unroll
        for (int b = 0; b < 4; b++)
            #pragma unroll
            for (int c = 0; c < 4; c++) acc[a][b][c] = 0.f;

    // ldmatrix lane-address components
    const int rA = lane & 15, hA = lane >> 4;          // A: rows, k-half
    const int qB = lane >> 3, r8 = lane & 7;           // B: quad, row-in-8
    const int bRow = (qB >> 1) * 8 + r8, bHalf = qB & 1;

    auto load_stage = [&](int st, int kk) {
        uint32_t base = sb + (uint32_t)st * STAGE_BYTES;
        #pragma unroll
        for (int mat = 0; mat < 4; mat++) {
            const __nv_bfloat16* g = gsrc[mat] + kk;
            uint32_t mb = base + (uint32_t)mat * MAT_BYTES;
            #pragma unroll
            for (int j = 0; j < 4; j++) {
                int idx = tid + j * 256;
                int row = idx >> 3, c = idx & 7;
                cp16(mb + (uint32_t)(row * 144 + c * 16), g + (size_t)row * K + c * 8);
            }
        }
        CP_COMMIT();
    };

    auto compute_stage = [&](int st) {
        uint32_t base = sb + (uint32_t)st * STAGE_BYTES;
        const uint32_t sAh = base, sAl = base + MAT_BYTES;
        const uint32_t sBh = base + 2 * MAT_BYTES, sBl = base + 3 * MAT_BYTES;
        #pragma unroll
        for (int ks = 0; ks < 4; ks++) {
            uint32_t aH[4][4], aL[4][4], bH[2][4], bL[2][4];
            #pragma unroll
            for (int mt = 0; mt < 4; mt++) {
                uint32_t off = (uint32_t)((wm + mt * 16 + rA) * 144 + ks * 32 + hA * 16);
                LDM4(aH[mt], sAh + off);
                LDM4(aL[mt], sAl + off);
            }
            #pragma unroll
            for (int bt = 0; bt < 2; bt++) {
                uint32_t off = (uint32_t)((wn + bt * 16 + bRow) * 144 + ks * 32 + bHalf * 16);
                LDM4(bH[bt], sBh + off);
                LDM4(bL[bt], sBl + off);
            }
            #pragma unroll
            for (int mt = 0; mt < 4; mt++)
                #pragma unroll
                for (int nt = 0; nt < 4; nt++) {
                    const int bt = nt >> 1, p = (nt & 1) * 2;
                    MMA(acc[mt][nt], aH[mt], bH[bt][p], bH[bt][p + 1]);   // Ahi*Bhi
                    MMA(acc[mt][nt], aH[mt], bL[bt][p], bL[bt][p + 1]);   // Ahi*Blo
                    MMA(acc[mt][nt], aL[mt], bH[bt][p], bH[bt][p + 1]);   // Alo*Bhi
                }
        }
    };

    load_stage(0, 0);
    for (int ic = 0; ic < nc; ic++) {
        if (ic + 1 < nc) { load_stage((ic + 1) & 1, (ic + 1) << 6); CP_WAIT(1); }
        else             { CP_WAIT(0); }
        __syncthreads();
        compute_stage(ic & 1);
        __syncthreads();
    }

    // Epilogue: write accumulators (fragment layout -> float2 stores)
    const int rowb = lane >> 2, colb = (lane & 3) * 2;
    #pragma unroll
    for (int mt = 0; mt < 4; mt++)
        #pragma unroll
        for (int nt = 0; nt < 4; nt++) {
            const int r = m0 + wm + mt * 16 + rowb;
            const int cI = n0 + wn + nt * 8 + colb;
            *(float2*)&C[(size_t)r * N + cI]       = make_float2(acc[mt][nt][0], acc[mt][nt][1]);
            *(float2*)&C[(size_t)(r + 8) * N + cI] = make_float2(acc[mt][nt][2], acc[mt][nt][3]);
        }
}

// ---------------------------------------------------------------------------
// Causal flash attention, fp32 (heavy tiles launch first).
// ---------------------------------------------------------------------------
__global__ __launch_bounds__(128) void flash_kernel(
    const float* __restrict__ qkv, float* __restrict__ out)
{
    __shared__ float sK[KT * HD];   // 16 KB
    __shared__ float sV[KT * HD];   // 16 KB

    const int t  = threadIdx.x;
    const int q0 = (gridDim.x - 1 - blockIdx.x) * QT;
    const int h  = blockIdx.y;
    const int b  = blockIdx.z;

    const float* base = qkv + (size_t)b * SLEN * 3 * DMODEL + h * HD;
    const int qi = q0 + t;

    float q[HD];
    {
        const float4* q4 = reinterpret_cast<const float4*>(base + (size_t)qi * 3 * DMODEL);
        #pragma unroll
        for (int d4 = 0; d4 < HD / 4; d4++) {
            float4 v = q4[d4];
            q[4 * d4 + 0] = v.x; q[4 * d4 + 1] = v.y;
            q[4 * d4 + 2] = v.z; q[4 * d4 + 3] = v.w;
        }
    }

    float m = -INFINITY, l = 0.f;
    float acc[HD];
    #pragma unroll
    for (int d = 0; d < HD; d++) acc[d] = 0.f;

    const float scale = 0.125f;

    for (int k0 = 0; k0 < q0 + QT; k0 += KT) {
        __syncthreads();
        const float* kb = base + (size_t)k0 * 3 * DMODEL + DMODEL;
        const float* vb = kb + DMODEL;
        for (int i = t; i < KT * (HD / 4); i += 128) {
            int r = i / (HD / 4), c = i % (HD / 4);
            reinterpret_cast<float4*>(sK)[i] =
                reinterpret_cast<const float4*>(kb + (size_t)r * 3 * DMODEL)[c];
            reinterpret_cast<float4*>(sV)[i] =
                reinterpret_cast<const float4*>(vb + (size_t)r * 3 * DMODEL)[c];
        }
        __syncthreads();

        for (int j0 = 0; j0 < KT; j0 += 16) {
            if (k0 + j0 > qi) break;
            float sv[16];
            float mc = -INFINITY;
            #pragma unroll
            for (int jj = 0; jj < 16; jj++) {
                const int j = j0 + jj;
                const float4* K4 = reinterpret_cast<const float4*>(sK + j * HD);
                float s0 = 0.f, s1 = 0.f, s2 = 0.f, s3 = 0.f;
                #pragma unroll
                for (int d4 = 0; d4 < HD / 4; d4++) {
                    float4 kk = K4[d4];
                    s0 += q[4 * d4 + 0] * kk.x;
                    s1 += q[4 * d4 + 1] * kk.y;
                    s2 += q[4 * d4 + 2] * kk.z;
                    s3 += q[4 * d4 + 3] * kk.w;
                }
                float s = ((s0 + s1) + (s2 + s3)) * scale;
                if (k0 + j > qi) s = -INFINITY;
                sv[jj] = s;
                mc = fmaxf(mc, s);
            }
            const float mnew = fmaxf(m, mc);
            const float corr = __expf(m - mnew);
            l *= corr;
            #pragma unroll
            for (int d = 0; d < HD; d++) acc[d] *= corr;
            #pragma unroll
            for (int jj = 0; jj < 16; jj++) {
                const int j = j0 + jj;
                const float p = (k0 + j <= qi) ? __expf(sv[jj] - mnew) : 0.f;
                l += p;
                const float4* V4 = reinterpret_cast<const float4*>(sV + j * HD);
                #pragma unroll
                for (int d4 = 0; d4 < HD / 4; d4++) {
                    float4 vv = V4[d4];
                    acc[4 * d4 + 0] += p * vv.x;
                    acc[4 * d4 + 1] += p * vv.y;
                    acc[4 * d4 + 2] += p * vv.z;
                    acc[4 * d4 + 3] += p * vv.w;
                }
            }
            m = mnew;
        }
    }

    const float inv = 1.f / l;
    float* ob = out + ((size_t)(b * SLEN + qi)) * DMODEL + h * HD;
    #pragma unroll
    for (int d4 = 0; d4 < HD / 4; d4++) {
        float4 o = make_float4(acc[4 * d4 + 0] * inv, acc[4 * d4 + 1] * inv,
                               acc[4 * d4 + 2] * inv, acc[4 * d4 + 3] * inv);
        reinterpret_cast<float4*>(ob)[d4] = o;
    }
}

// ---------------------------------------------------------------------------
// kernel_launch
// ---------------------------------------------------------------------------
extern "C" void kernel_launch(void* const* d_in, const int* in_sizes, int n_in,
                              void* d_out, int out_size)
{
    const float* x     = (const float*)d_in[0];
    const float* w_qkv = (const float*)d_in[1];
    const float* w_out = (const float*)d_in[2];
    float* out = (float*)d_out;

    float *qkv, *att;
    __nv_bfloat16 *xhi, *xlo, *w1hi, *w1lo, *w2hi, *w2lo, *ahi, *alo;
    cudaGetSymbolAddress((void**)&qkv, g_qkv);
    cudaGetSymbolAddress((void**)&att, g_att);
    cudaGetSymbolAddress((void**)&xhi, g_xhi);
    cudaGetSymbolAddress((void**)&xlo, g_xlo);
    cudaGetSymbolAddress((void**)&w1hi, g_w1hi);
    cudaGetSymbolAddress((void**)&w1lo, g_w1lo);
    cudaGetSymbolAddress((void**)&w2hi, g_w2hi);
    cudaGetSymbolAddress((void**)&w2lo, g_w2lo);
    cudaGetSymbolAddress((void**)&ahi, g_ahi);
    cudaGetSymbolAddress((void**)&alo, g_alo);

    cudaFuncSetAttribute(gemm_mma3, cudaFuncAttributeMaxDynamicSharedMemorySize, GSMEM_BYTES);

    const int M = MDIM;

    // Split inputs / weights into bf16 hi/lo (weights also transposed to [N,K])
    {
        int n4 = M * DMODEL / 4;
        split_fp32<<<(n4 + 255) / 256, 256>>>(x, xhi, xlo, n4);
    }
    split_transpose<<<dim3(3 * DMODEL / 32, DMODEL / 32), dim3(32, 8)>>>(w_qkv, w1hi, w1lo, DMODEL, 3 * DMODEL);
    split_transpose<<<dim3(DMODEL / 32, DMODEL / 32), dim3(32, 8)>>>(w_out, w2hi, w2lo, DMODEL, DMODEL);

    // 1) qkv = x @ w_qkv   (mma.sync, 3-term fp32 emulation)
    gemm_mma3<<<dim3(3 * DMODEL / 128, M / 128), 256, GSMEM_BYTES>>>(
        xhi, xlo, w1hi, w1lo, qkv, M, 3 * DMODEL, DMODEL);

    // 2) causal flash attention
    flash_kernel<<<dim3(SLEN / QT, HEADS, BATCH), 128>>>(qkv, att);

    // 3) split attention output, then out = att @ w_out
    {
        int n4 = M * DMODEL / 4;
        split_fp32<<<(n4 + 255) / 256, 256>>>(att, ahi, alo, n4);
    }
    gemm_mma3<<<dim3(DMODEL / 128, M / 128), 256, GSMEM_BYTES>>>(
        ahi, alo, w2hi, w2lo, out, M, DMODEL, DMODEL);
}

// round 5
// speedup vs baseline: 3.1198x; 2.1781x over previous
#include <cuda_runtime.h>
#include <cuda_bf16.h>
#include <cstdint>

// Problem constants
#define BATCH 2
#define SLEN 2048
#define DMODEL 1024
#define HEADS 16
#define HD 64
#define MDIM (BATCH * SLEN)   // 4096
#define D3 (3 * DMODEL)       // 3072

// ---------------------------------------------------------------------------
// Scratch (device globals; no allocations allowed)
// ---------------------------------------------------------------------------
__device__ __nv_bfloat16 g_xhi[(size_t)MDIM * DMODEL];
__device__ __nv_bfloat16 g_xlo[(size_t)MDIM * DMODEL];
__device__ __nv_bfloat16 g_w1hi[(size_t)D3 * DMODEL];   // w_qkv^T [3D, D]
__device__ __nv_bfloat16 g_w1lo[(size_t)D3 * DMODEL];
__device__ __nv_bfloat16 g_w2hi[(size_t)DMODEL * DMODEL]; // w_out^T [D, D]
__device__ __nv_bfloat16 g_w2lo[(size_t)DMODEL * DMODEL];
__device__ __nv_bfloat16 g_qkvhi[(size_t)MDIM * D3];    // GEMM1 split output
__device__ __nv_bfloat16 g_qkvlo[(size_t)MDIM * D3];
__device__ __nv_bfloat16 g_ahi[(size_t)MDIM * DMODEL];  // attention split output
__device__ __nv_bfloat16 g_alo[(size_t)MDIM * DMODEL];

// ---------------------------------------------------------------------------
// PTX helpers (sm_80+ only — harness targets base sm_100)
// ---------------------------------------------------------------------------
__device__ __forceinline__ uint32_t smem_u32(const void* p) {
    uint32_t a;
    asm("{ .reg .u64 t; cvta.to.shared.u64 t, %1; cvt.u32.u64 %0, t; }" : "=r"(a) : "l"(p));
    return a;
}
__device__ __forceinline__ void cp16(uint32_t dst, const void* src) {
    asm volatile("cp.async.cg.shared.global [%0], [%1], 16;" :: "r"(dst), "l"(src) : "memory");
}
#define CP_COMMIT() asm volatile("cp.async.commit_group;" ::: "memory")
#define CP_WAIT(n)  asm volatile("cp.async.wait_group %0;" :: "n"(n) : "memory")

#define LDM4(r, addr) \
    asm volatile("ldmatrix.sync.aligned.m8n8.x4.shared.b16 {%0,%1,%2,%3}, [%4];" \
        : "=r"((r)[0]), "=r"((r)[1]), "=r"((r)[2]), "=r"((r)[3]) : "r"(addr))
#define LDM4T(r, addr) \
    asm volatile("ldmatrix.sync.aligned.m8n8.x4.trans.shared.b16 {%0,%1,%2,%3}, [%4];" \
        : "=r"((r)[0]), "=r"((r)[1]), "=r"((r)[2]), "=r"((r)[3]) : "r"(addr))

#define MMA(d, a, b0, b1) \
    asm volatile("mma.sync.aligned.m16n8k16.row.col.f32.bf16.bf16.f32 " \
        "{%0,%1,%2,%3}, {%4,%5,%6,%7}, {%8,%9}, {%0,%1,%2,%3};" \
        : "+f"((d)[0]), "+f"((d)[1]), "+f"((d)[2]), "+f"((d)[3]) \
        : "r"((a)[0]), "r"((a)[1]), "r"((a)[2]), "r"((a)[3]), "r"(b0), "r"(b1))

__device__ __forceinline__ uint32_t packb(float a, float b) {
    __nv_bfloat162 t = __floats2bfloat162_rn(a, b);
    return *reinterpret_cast<uint32_t*>(&t);
}
__device__ __forceinline__ float bhi(float v) {
    return __bfloat162float(__float2bfloat16(v));
}

// Fast exp2: deg-4 poly + exponent stuffing. x <= 0 expected; ~1e-6 rel err.
__device__ __forceinline__ float exp2_fast(float x) {
    x = fmaxf(x, -126.0f);
    int xi = __float2int_rd(x);
    float f = x - (float)xi;
    float p = 0.0135557472f;
    p = fmaf(p, f, 0.0520323690f);
    p = fmaf(p, f, 0.2413797743f);
    p = fmaf(p, f, 0.6930321187f);
    p = fmaf(p, f, 1.0f);
    return __int_as_float((xi + 127) << 23) * p;
}

#define CEXP 0.1803368801111204f   // 0.125 * log2(e)

// ---------------------------------------------------------------------------
// Split fp32 -> (hi, lo) bf16 elementwise
// ---------------------------------------------------------------------------
__global__ __launch_bounds__(256) void split_fp32(
    const float* __restrict__ src, __nv_bfloat16* __restrict__ hi,
    __nv_bfloat16* __restrict__ lo, int n4)
{
    int i = blockIdx.x * blockDim.x + threadIdx.x;
    if (i >= n4) return;
    float4 v = reinterpret_cast<const float4*>(src)[i];
    float f[4] = {v.x, v.y, v.z, v.w};
    uint2 hp, lp;
    hp.x = packb(f[0], f[1]); hp.y = packb(f[2], f[3]);
    lp.x = packb(f[0] - bhi(f[0]), f[1] - bhi(f[1]));
    lp.y = packb(f[2] - bhi(f[2]), f[3] - bhi(f[3]));
    reinterpret_cast<uint2*>(hi)[i] = hp;
    reinterpret_cast<uint2*>(lo)[i] = lp;
}

// ---------------------------------------------------------------------------
// Split + transpose: src [R, C] fp32 -> hiT, loT [C, R] bf16
// ---------------------------------------------------------------------------
__global__ __launch_bounds__(256) void split_transpose(
    const float* __restrict__ src, __nv_bfloat16* __restrict__ hiT,
    __nv_bfloat16* __restrict__ loT, int R, int C)
{
    __shared__ float t[32][33];
    const int c0 = blockIdx.x * 32, r0 = blockIdx.y * 32;
    const int tx = threadIdx.x, ty = threadIdx.y;   // 32 x 8
    #pragma unroll
    for (int j = 0; j < 4; j++)
        t[ty + 8 * j][tx] = src[(size_t)(r0 + ty + 8 * j) * C + c0 + tx];
    __syncthreads();
    #pragma unroll
    for (int j = 0; j < 4; j++) {
        float v = t[tx][ty + 8 * j];
        size_t o = (size_t)(c0 + ty + 8 * j) * R + r0 + tx;
        hiT[o] = __float2bfloat16(v);
        loT[o] = __float2bfloat16(v - bhi(v));
    }
}

// ---------------------------------------------------------------------------
// Warp-MMA GEMM, 3-term bf16 split emulation of fp32.
// SPLIT_OUT=1: write hi/lo bf16 outputs; else fp32.
// ---------------------------------------------------------------------------
#define MAT_BYTES 18432        // 128 rows * 144 B
#define STAGE_BYTES 73728
#define GSMEM_BYTES 147456

template<int SPLIT_OUT>
__global__ __launch_bounds__(256, 1) void gemm_mma3(
    const __nv_bfloat16* __restrict__ Ahi, const __nv_bfloat16* __restrict__ Alo,
    const __nv_bfloat16* __restrict__ BThi, const __nv_bfloat16* __restrict__ BTlo,
    float* __restrict__ C, __nv_bfloat16* __restrict__ Chi, __nv_bfloat16* __restrict__ Clo,
    int M, int N, int K)
{
    extern __shared__ char smem[];
    const uint32_t sb = smem_u32(smem);
    const int tid = threadIdx.x;
    const int wid = tid >> 5, lane = tid & 31;
    const int m0 = blockIdx.y << 7, n0 = blockIdx.x << 7;
    const int wm = (wid >> 2) * 64, wn = (wid & 3) * 32;
    const int nc = K >> 6;

    const __nv_bfloat16* gsrc[4] = {
        Ahi + (size_t)m0 * K, Alo + (size_t)m0 * K,
        BThi + (size_t)n0 * K, BTlo + (size_t)n0 * K };

    float acc[4][4][4];
    #pragma unroll
    for (int a = 0; a < 4; a++)
        #pragma unroll
        for (int b = 0; b < 4; b++)
            #pragma unroll
            for (int c = 0; c < 4; c++) acc[a][b][c] = 0.f;

    const int rA = lane & 15, hA = lane >> 4;
    const int qB = lane >> 3, r8 = lane & 7;
    const int bRow = (qB >> 1) * 8 + r8, bHalf = qB & 1;

    auto load_stage = [&](int st, int kk) {
        uint32_t base = sb + (uint32_t)st * STAGE_BYTES;
        #pragma unroll
        for (int mat = 0; mat < 4; mat++) {
            const __nv_bfloat16* g = gsrc[mat] + kk;
            uint32_t mb = base + (uint32_t)mat * MAT_BYTES;
            #pragma unroll
            for (int j = 0; j < 4; j++) {
                int idx = tid + j * 256;
                int row = idx >> 3, c = idx & 7;
                cp16(mb + (uint32_t)(row * 144 + c * 16), g + (size_t)row * K + c * 8);
            }
        }
        CP_COMMIT();
    };

    auto compute_stage = [&](int st) {
        uint32_t base = sb + (uint32_t)st * STAGE_BYTES;
        const uint32_t sAh = base, sAl = base + MAT_BYTES;
        const uint32_t sBh = base + 2 * MAT_BYTES, sBl = base + 3 * MAT_BYTES;
        #pragma unroll
        for (int ks = 0; ks < 4; ks++) {
            uint32_t aH[4][4], aL[4][4], bH[2][4], bL[2][4];
            #pragma unroll
            for (int mt = 0; mt < 4; mt++) {
                uint32_t off = (uint32_t)((wm + mt * 16 + rA) * 144 + ks * 32 + hA * 16);
                LDM4(aH[mt], sAh + off);
                LDM4(aL[mt], sAl + off);
            }
            #pragma unroll
            for (int bt = 0; bt < 2; bt++) {
                uint32_t off = (uint32_t)((wn + bt * 16 + bRow) * 144 + ks * 32 + bHalf * 16);
                LDM4(bH[bt], sBh + off);
                LDM4(bL[bt], sBl + off);
            }
            #pragma unroll
            for (int mt = 0; mt < 4; mt++)
                #pragma unroll
                for (int nt = 0; nt < 4; nt++) {
                    const int bt = nt >> 1, p = (nt & 1) * 2;
                    MMA(acc[mt][nt], aH[mt], bH[bt][p], bH[bt][p + 1]);
                    MMA(acc[mt][nt], aH[mt], bL[bt][p], bL[bt][p + 1]);
                    MMA(acc[mt][nt], aL[mt], bH[bt][p], bH[bt][p + 1]);
                }
        }
    };

    load_stage(0, 0);
    for (int ic = 0; ic < nc; ic++) {
        if (ic + 1 < nc) { load_stage((ic + 1) & 1, (ic + 1) << 6); CP_WAIT(1); }
        else             { CP_WAIT(0); }
        __syncthreads();
        compute_stage(ic & 1);
        __syncthreads();
    }

    const int rowb = lane >> 2, colb = (lane & 3) * 2;
    #pragma unroll
    for (int mt = 0; mt < 4; mt++)
        #pragma unroll
        for (int nt = 0; nt < 4; nt++) {
            const int r = m0 + wm + mt * 16 + rowb;
            const int cI = n0 + wn + nt * 8 + colb;
            float v0 = acc[mt][nt][0], v1 = acc[mt][nt][1];
            float v2 = acc[mt][nt][2], v3 = acc[mt][nt][3];
            if (SPLIT_OUT) {
                *(uint32_t*)&Chi[(size_t)r * N + cI] = packb(v0, v1);
                *(uint32_t*)&Clo[(size_t)r * N + cI] = packb(v0 - bhi(v0), v1 - bhi(v1));
                *(uint32_t*)&Chi[(size_t)(r + 8) * N + cI] = packb(v2, v3);
                *(uint32_t*)&Clo[(size_t)(r + 8) * N + cI] = packb(v2 - bhi(v2), v3 - bhi(v3));
            } else {
                *(float2*)&C[(size_t)r * N + cI]       = make_float2(v0, v1);
                *(float2*)&C[(size_t)(r + 8) * N + cI] = make_float2(v2, v3);
            }
        }
}

// ---------------------------------------------------------------------------
// Tensor-core causal flash attention (FA2-style), 3-term split for QK and PV.
// Reads split qkv (bf16 hi/lo), writes split attention output (bf16 hi/lo).
// CTA: 256 threads (8 warps), q-tile 128 (16 rows/warp), k-tile 64.
// SMEM: Qh,Ql [128x144B] + 2 stages of {Kh,Kl,Vh,Vl} [64x144B each].
// ---------------------------------------------------------------------------
#define FQ_BYTES 18432          // 128*144
#define FKV_MAT 9216            // 64*144
#define FSTAGE (4 * FKV_MAT)    // 36864
#define FSMEM (2 * FQ_BYTES + 2 * FSTAGE)   // 110592

__global__ __launch_bounds__(256) void flash_mma(
    const __nv_bfloat16* __restrict__ qhi, const __nv_bfloat16* __restrict__ qlo,
    __nv_bfloat16* __restrict__ outhi, __nv_bfloat16* __restrict__ outlo)
{
    extern __shared__ char smem[];
    const uint32_t sb = smem_u32(smem);
    const uint32_t sQh = sb, sQl = sb + FQ_BYTES;
    const uint32_t sStage = sb + 2 * FQ_BYTES;

    const int tid = threadIdx.x, wid = tid >> 5, lane = tid & 31;
    const int q0 = ((int)gridDim.x - 1 - (int)blockIdx.x) * 128;
    const int h = blockIdx.y, b = blockIdx.z;
    const int qrow0 = q0 + wid * 16;

    const __nv_bfloat16* bhiP = qhi + (size_t)b * SLEN * D3 + h * HD;
    const __nv_bfloat16* bloP = qlo + (size_t)b * SLEN * D3 + h * HD;

    // ldmatrix lane-address components
    const int rA = lane & 15, hA = lane >> 4;              // A frag (Q, 16 rows)
    const int qB = lane >> 3, r8 = lane & 7;               // B frag (K rows)
    const int bRow = (qB >> 1) * 8 + r8, bHalf = qB & 1;
    const int grp = lane >> 3, l8 = lane & 7;              // V trans frag

    // Stage Q tile (hi+lo): 2048 x 16B chunks
    {
        #pragma unroll
        for (int j = 0; j < 8; j++) {
            int idx = tid + j * 256;
            int mat = idx >> 10, row = (idx >> 3) & 127, c = idx & 7;
            const __nv_bfloat16* src = (mat ? bloP : bhiP) + (size_t)(q0 + row) * D3 + c * 8;
            cp16((mat ? sQl : sQh) + (uint32_t)(row * 144 + c * 16), src);
        }
    }

    const int nk = q0 / 64 + 2;

    auto load_kv = [&](int st, int k0) {
        uint32_t base = sStage + (uint32_t)st * FSTAGE;
        #pragma unroll
        for (int j = 0; j < 8; j++) {
            int idx = tid + j * 256;
            int mat = idx >> 9, row = (idx >> 3) & 63, c = idx & 7;
            // mats: 0=Kh 1=Kl 2=Vh 3=Vl ; K at +DMODEL, V at +2*DMODEL
            const __nv_bfloat16* base_g = (mat & 1) ? bloP : bhiP;
            int seg = (mat >> 1) ? 2 * DMODEL : DMODEL;
            const __nv_bfloat16* src = base_g + (size_t)(k0 + row) * D3 + seg + c * 8;
            cp16(base + (uint32_t)mat * FKV_MAT + (uint32_t)(row * 144 + c * 16), src);
        }
        CP_COMMIT();
    };

    float oacc[8][4];
    #pragma unroll
    for (int i = 0; i < 8; i++)
        #pragma unroll
        for (int j = 0; j < 4; j++) oacc[i][j] = 0.f;
    float m0 = -1e30f, m1 = -1e30f, l0 = 0.f, l1 = 0.f;

    load_kv(0, 0);
    CP_COMMIT();   // close the (Q + stage0) group boundary cleanly

    for (int it = 0; it < nk; it++) {
        const int k0 = it * 64;
        if (it + 1 < nk) { load_kv((it + 1) & 1, (it + 1) * 64); CP_WAIT(1); }
        else             { CP_WAIT(0); }
        __syncthreads();

        if (k0 <= qrow0 + 15) {
            const uint32_t st = sStage + (uint32_t)(it & 1) * FSTAGE;
            const uint32_t sKh = st, sKl = st + FKV_MAT;
            const uint32_t sVh = st + 2 * FKV_MAT, sVl = st + 3 * FKV_MAT;

            // ---- S = Q K^T (3-term split), 16x64 per warp
            float sfrag[8][4];
            #pragma unroll
            for (int i = 0; i < 8; i++)
                #pragma unroll
                for (int j = 0; j < 4; j++) sfrag[i][j] = 0.f;

            #pragma unroll
            for (int ks = 0; ks < 4; ks++) {
                uint32_t aH[4], aL[4], kh[4][4], kl[4][4];
                uint32_t aoff = (uint32_t)((wid * 16 + rA) * 144 + ks * 32 + hA * 16);
                LDM4(aH, sQh + aoff);
                LDM4(aL, sQl + aoff);
                #pragma unroll
                for (int bt = 0; bt < 4; bt++) {
                    uint32_t off = (uint32_t)((bt * 16 + bRow) * 144 + ks * 32 + bHalf * 16);
                    LDM4(kh[bt], sKh + off);
                    LDM4(kl[bt], sKl + off);
                }
                #pragma unroll
                for (int nt = 0; nt < 8; nt++) {
                    const int bt = nt >> 1, p = (nt & 1) * 2;
                    MMA(sfrag[nt], aH, kh[bt][p], kh[bt][p + 1]);
                    MMA(sfrag[nt], aH, kl[bt][p], kl[bt][p + 1]);
                    MMA(sfrag[nt], aL, kh[bt][p], kh[bt][p + 1]);
                }
            }

            // ---- causal mask on diagonal tiles
            const int row0 = qrow0 + (lane >> 2), row1 = row0 + 8;
            if (k0 + 63 > qrow0) {
                #pragma unroll
                for (int nt = 0; nt < 8; nt++) {
                    int col = k0 + nt * 8 + ((lane & 3) << 1);
                    if (col > row0)     sfrag[nt][0] = -1e30f;
                    if (col + 1 > row0) sfrag[nt][1] = -1e30f;
                    if (col > row1)     sfrag[nt][2] = -1e30f;
                    if (col + 1 > row1) sfrag[nt][3] = -1e30f;
                }
            }

            // ---- online softmax (scaled by 0.125 via CEXP)
            float mc0 = -1e30f, mc1 = -1e30f;
            #pragma unroll
            for (int nt = 0; nt < 8; nt++) {
                mc0 = fmaxf(mc0, fmaxf(sfrag[nt][0], sfrag[nt][1]));
                mc1 = fmaxf(mc1, fmaxf(sfrag[nt][2], sfrag[nt][3]));
            }
            mc0 = fmaxf(mc0, __shfl_xor_sync(0xffffffffu, mc0, 1));
            mc0 = fmaxf(mc0, __shfl_xor_sync(0xffffffffu, mc0, 2));
            mc1 = fmaxf(mc1, __shfl_xor_sync(0xffffffffu, mc1, 1));
            mc1 = fmaxf(mc1, __shfl_xor_sync(0xffffffffu, mc1, 2));
            const float mn0 = fmaxf(m0, mc0), mn1 = fmaxf(m1, mc1);
            const float corr0 = exp2_fast((m0 - mn0) * CEXP);
            const float corr1 = exp2_fast((m1 - mn1) * CEXP);
            m0 = mn0; m1 = mn1;

            float rs0 = 0.f, rs1 = 0.f;
            #pragma unroll
            for (int nt = 0; nt < 8; nt++) {
                sfrag[nt][0] = exp2_fast((sfrag[nt][0] - mn0) * CEXP);
                sfrag[nt][1] = exp2_fast((sfrag[nt][1] - mn0) * CEXP);
                sfrag[nt][2] = exp2_fast((sfrag[nt][2] - mn1) * CEXP);
                sfrag[nt][3] = exp2_fast((sfrag[nt][3] - mn1) * CEXP);
                rs0 += sfrag[nt][0] + sfrag[nt][1];
                rs1 += sfrag[nt][2] + sfrag[nt][3];
            }
            rs0 += __shfl_xor_sync(0xffffffffu, rs0, 1);
            rs0 += __shfl_xor_sync(0xffffffffu, rs0, 2);
            rs1 += __shfl_xor_sync(0xffffffffu, rs1, 1);
            rs1 += __shfl_xor_sync(0xffffffffu, rs1, 2);
            l0 = l0 * corr0 + rs0;
            l1 = l1 * corr1 + rs1;
            #pragma unroll
            for (int nt = 0; nt < 8; nt++) {
                oacc[nt][0] *= corr0; oacc[nt][1] *= corr0;
                oacc[nt][2] *= corr1; oacc[nt][3] *= corr1;
            }

            // ---- O += P V (3-term split)
            #pragma unroll
            for (int t = 0; t < 4; t++) {
                // P a-frags from S c-frags (pure register packing)
                uint32_t phi[4], plo[4];
                {
                    float p0 = sfrag[2 * t][0], p1 = sfrag[2 * t][1];
                    float p2 = sfrag[2 * t][2], p3 = sfrag[2 * t][3];
                    float p4 = sfrag[2 * t + 1][0], p5 = sfrag[2 * t + 1][1];
                    float p6 = sfrag[2 * t + 1][2], p7 = sfrag[2 * t + 1][3];
                    phi[0] = packb(p0, p1); phi[1] = packb(p2, p3);
                    phi[2] = packb(p4, p5); phi[3] = packb(p6, p7);
                    plo[0] = packb(p0 - bhi(p0), p1 - bhi(p1));
                    plo[1] = packb(p2 - bhi(p2), p3 - bhi(p3));
                    plo[2] = packb(p4 - bhi(p4), p5 - bhi(p5));
                    plo[3] = packb(p6 - bhi(p6), p7 - bhi(p7));
                }
                #pragma unroll
                for (int np = 0; np < 4; np++) {
                    uint32_t vh[4], vl[4];
                    uint32_t off = (uint32_t)((t * 16 + (grp & 1) * 8 + l8) * 144 +
                                              (np * 16 + (grp >> 1) * 8) * 2);
                    LDM4T(vh, sVh + off);
                    LDM4T(vl, sVl + off);
                    const int nt0 = np * 2;
                    MMA(oacc[nt0], phi, vh[0], vh[1]);
                    MMA(oacc[nt0], phi, vl[0], vl[1]);
                    MMA(oacc[nt0], plo, vh[0], vh[1]);
                    MMA(oacc[nt0 + 1], phi, vh[2], vh[3]);
                    MMA(oacc[nt0 + 1], phi, vl[2], vl[3]);
                    MMA(oacc[nt0 + 1], plo, vh[2], vh[3]);
                }
            }
        }
        __syncthreads();
    }

    // ---- finalize: O /= l, write split bf16 output [B*S, D]
    const float inv0 = 1.f / l0, inv1 = 1.f / l1;
    const int row0 = q0 + wid * 16 + (lane >> 2);
    const int colb = h * HD + (lane & 3) * 2;
    #pragma unroll
    for (int nt = 0; nt < 8; nt++) {
        float v0 = oacc[nt][0] * inv0, v1 = oacc[nt][1] * inv0;
        float v2 = oacc[nt][2] * inv1, v3 = oacc[nt][3] * inv1;
        size_t o0 = (size_t)(b * SLEN + row0) * DMODEL + colb + nt * 8;
        size_t o1 = (size_t)(b * SLEN + row0 + 8) * DMODEL + colb + nt * 8;
        *(uint32_t*)&outhi[o0] = packb(v0, v1);
        *(uint32_t*)&outlo[o0] = packb(v0 - bhi(v0), v1 - bhi(v1));
        *(uint32_t*)&outhi[o1] = packb(v2, v3);
        *(uint32_t*)&outlo[o1] = packb(v2 - bhi(v2), v3 - bhi(v3));
    }
}

// ---------------------------------------------------------------------------
// kernel_launch
// ---------------------------------------------------------------------------
extern "C" void kernel_launch(void* const* d_in, const int* in_sizes, int n_in,
                              void* d_out, int out_size)
{
    const float* x     = (const float*)d_in[0];
    const float* w_qkv = (const float*)d_in[1];
    const float* w_out = (const float*)d_in[2];
    float* out = (float*)d_out;

    __nv_bfloat16 *xhi, *xlo, *w1hi, *w1lo, *w2hi, *w2lo, *qhi, *qlo, *ahi, *alo;
    cudaGetSymbolAddress((void**)&xhi, g_xhi);
    cudaGetSymbolAddress((void**)&xlo, g_xlo);
    cudaGetSymbolAddress((void**)&w1hi, g_w1hi);
    cudaGetSymbolAddress((void**)&w1lo, g_w1lo);
    cudaGetSymbolAddress((void**)&w2hi, g_w2hi);
    cudaGetSymbolAddress((void**)&w2lo, g_w2lo);
    cudaGetSymbolAddress((void**)&qhi, g_qkvhi);
    cudaGetSymbolAddress((void**)&qlo, g_qkvlo);
    cudaGetSymbolAddress((void**)&ahi, g_ahi);
    cudaGetSymbolAddress((void**)&alo, g_alo);

    cudaFuncSetAttribute(gemm_mma3<0>, cudaFuncAttributeMaxDynamicSharedMemorySize, GSMEM_BYTES);
    cudaFuncSetAttribute(gemm_mma3<1>, cudaFuncAttributeMaxDynamicSharedMemorySize, GSMEM_BYTES);
    cudaFuncSetAttribute(flash_mma, cudaFuncAttributeMaxDynamicSharedMemorySize, FSMEM);

    const int M = MDIM;

    // Split x; split+transpose weights
    split_fp32<<<(M * DMODEL / 4 + 255) / 256, 256>>>(x, xhi, xlo, M * DMODEL / 4);
    split_transpose<<<dim3(D3 / 32, DMODEL / 32), dim3(32, 8)>>>(w_qkv, w1hi, w1lo, DMODEL, D3);
    split_transpose<<<dim3(DMODEL / 32, DMODEL / 32), dim3(32, 8)>>>(w_out, w2hi, w2lo, DMODEL, DMODEL);

    // 1) qkv (split bf16 out) = x @ w_qkv
    gemm_mma3<1><<<dim3(D3 / 128, M / 128), 256, GSMEM_BYTES>>>(
        xhi, xlo, w1hi, w1lo, nullptr, qhi, qlo, M, D3, DMODEL);

    // 2) tensor-core causal flash attention -> split bf16 att
    flash_mma<<<dim3(SLEN / 128, HEADS, BATCH), 256, FSMEM>>>(qhi, qlo, ahi, alo);

    // 3) out = att @ w_out (fp32 out)
    gemm_mma3<0><<<dim3(DMODEL / 128, M / 128), 256, GSMEM_BYTES>>>(
        ahi, alo, w2hi, w2lo, out, nullptr, nullptr, M, DMODEL, DMODEL);
}